// round 13
// baseline (speedup 1.0000x reference)
#include <cuda_runtime.h>
#include <cstdint>

#define BB 64
#define TT 512
#define DD 256
#define HH 512
#define NG 32            // groups of 8 CTAs
#define GC 8             // CTAs per group

typedef unsigned long long ull;

// Scratch (module-static; no runtime allocs)
__device__ float    g_xproj[(size_t)BB * TT * HH];   // 64 MB
__device__ float    g_z[NG][2][2][HH];               // [group][set][buf][col]
__device__ float2   g_part[NG][2][2][GC];            // [group][set][buf][cta]
__device__ unsigned g_flag[NG][2];                   // per-set step counters

__device__ __forceinline__ void ffma2(ull& acc, ull a, ull b) {
    asm volatile("fma.rn.f32x2 %0, %1, %2, %0;" : "+l"(acc) : "l"(a), "l"(b));
}
__device__ __forceinline__ ull add2(ull a, ull b) {
    ull r; asm("add.rn.f32x2 %0, %1, %2;" : "=l"(r) : "l"(a), "l"(b)); return r;
}
__device__ __forceinline__ ull pack2(float x, float y) {
    ull r; asm("mov.b64 %0, {%1, %2};" : "=l"(r) : "f"(x), "f"(y)); return r;
}
__device__ __forceinline__ float2 unpack2(ull v) {
    float2 r; asm("mov.b64 {%0, %1}, %2;" : "=f"(r.x), "=f"(r.y) : "l"(v)); return r;
}
__device__ __forceinline__ ull ldcg64(const float* p) {
    ull v; asm volatile("ld.global.cg.b64 %0, [%1];" : "=l"(v) : "l"(p)); return v;
}
__device__ __forceinline__ float4 ldcg128(const float4* p) {
    float4 v;
    asm volatile("ld.global.cg.v4.f32 {%0, %1, %2, %3}, [%4];"
                 : "=f"(v.x), "=f"(v.y), "=f"(v.z), "=f"(v.w) : "l"(p));
    return v;
}
__device__ __forceinline__ void stcg64(float* p, ull v) {
    asm volatile("st.global.cg.b64 [%0], %1;" :: "l"(p), "l"(v) : "memory");
}
__device__ __forceinline__ void stcg_f2(float2* p, float x, float y) {
    asm volatile("st.global.cg.v2.f32 [%0], {%1, %2};" :: "l"(p), "f"(x), "f"(y) : "memory");
}
__device__ __forceinline__ unsigned ld_acq(const unsigned* p) {
    unsigned v;
    asm volatile("ld.acquire.gpu.global.u32 %0, [%1];" : "=r"(v) : "l"(p) : "memory");
    return v;
}
__device__ __forceinline__ void red_rel_add(unsigned* p, unsigned v) {
    asm volatile("red.release.gpu.global.add.u32 [%0], %1;" :: "l"(p), "r"(v) : "memory");
}
__device__ __forceinline__ float ftanh(float x) {
    float xc = fminf(fmaxf(x, -9.f), 9.f);
    float e  = __expf(2.f * xc);
    return 1.f - __fdividef(2.f, e + 1.f);
}

// ---------------------------------------------------------------------------
// Kernel 1: xproj = inputs @ Wx + b  (f32x2 FMA). Also resets g_flag.
// ---------------------------------------------------------------------------
__global__ void __launch_bounds__(256) xproj_kernel(
    const float* __restrict__ A, const float* __restrict__ Wx,
    const float* __restrict__ bias) {
    __shared__ float As[16][128];
    __shared__ float Bs[16][64];

    const int tid = threadIdx.x;
    if (blockIdx.x == 0 && blockIdx.y == 0 && tid < NG * 2)
        ((unsigned*)g_flag)[tid] = 0;

    const int bm  = blockIdx.x * 128;
    const int bn  = blockIdx.y * 64;
    const int tx  = tid & 15;
    const int ty  = tid >> 4;

    ull acc[4][4];
#pragma unroll
    for (int p = 0; p < 4; ++p)
#pragma unroll
        for (int j = 0; j < 4; ++j) acc[p][j] = 0ull;

    const int m0 = tid >> 2;
    const int q  = tid & 3;
    const int kb = tid >> 4;
    const int jb = tid & 15;

    for (int kt = 0; kt < 16; ++kt) {
        float4 a0 = __ldg((const float4*)(A + (size_t)(bm + m0) * DD + kt * 16) + q);
        float4 a1 = __ldg((const float4*)(A + (size_t)(bm + m0 + 64) * DD + kt * 16) + q);
        float4 bv = __ldg((const float4*)(Wx + (size_t)(kt * 16 + kb) * HH + bn) + jb);
        __syncthreads();
        As[q * 4 + 0][m0] = a0.x; As[q * 4 + 1][m0] = a0.y;
        As[q * 4 + 2][m0] = a0.z; As[q * 4 + 3][m0] = a0.w;
        As[q * 4 + 0][m0 + 64] = a1.x; As[q * 4 + 1][m0 + 64] = a1.y;
        As[q * 4 + 2][m0 + 64] = a1.z; As[q * 4 + 3][m0 + 64] = a1.w;
        *(float4*)&Bs[kb][jb * 4] = bv;
        __syncthreads();
#pragma unroll
        for (int k = 0; k < 16; ++k) {
            ulonglong2 a01 = *(const ulonglong2*)&As[k][ty * 8];
            ulonglong2 a23 = *(const ulonglong2*)&As[k][ty * 8 + 4];
            float4 bq = *(const float4*)&Bs[k][tx * 4];
            ull b0 = pack2(bq.x, bq.x), b1 = pack2(bq.y, bq.y);
            ull b2 = pack2(bq.z, bq.z), b3 = pack2(bq.w, bq.w);
            ffma2(acc[0][0], a01.x, b0); ffma2(acc[0][1], a01.x, b1);
            ffma2(acc[0][2], a01.x, b2); ffma2(acc[0][3], a01.x, b3);
            ffma2(acc[1][0], a01.y, b0); ffma2(acc[1][1], a01.y, b1);
            ffma2(acc[1][2], a01.y, b2); ffma2(acc[1][3], a01.y, b3);
            ffma2(acc[2][0], a23.x, b0); ffma2(acc[2][1], a23.x, b1);
            ffma2(acc[2][2], a23.x, b2); ffma2(acc[2][3], a23.x, b3);
            ffma2(acc[3][0], a23.y, b0); ffma2(acc[3][1], a23.y, b1);
            ffma2(acc[3][2], a23.y, b2); ffma2(acc[3][3], a23.y, b3);
        }
    }

    float4 bb = __ldg((const float4*)(bias + bn) + tx);
#pragma unroll
    for (int p = 0; p < 4; ++p) {
        float2 c0 = unpack2(acc[p][0]), c1 = unpack2(acc[p][1]);
        float2 c2 = unpack2(acc[p][2]), c3 = unpack2(acc[p][3]);
        float4 ve, vo;
        ve.x = c0.x + bb.x; ve.y = c1.x + bb.y; ve.z = c2.x + bb.z; ve.w = c3.x + bb.w;
        vo.x = c0.y + bb.x; vo.y = c1.y + bb.y; vo.z = c2.y + bb.z; vo.w = c3.y + bb.w;
        int row = bm + ty * 8 + p * 2;
        *(float4*)&g_xproj[(size_t)row * HH + bn + tx * 4]       = ve;
        *(float4*)&g_xproj[(size_t)(row + 1) * HH + bn + tx * 4] = vo;
    }
}

// ---------------------------------------------------------------------------
// Kernel 2: persistent scan, 2 CTAs/SM, and TWO pipelined sets per CTA
// (set = one batch). Per step: C0, pub0 | C1, pub1, spin0 | E0, spin1 | E1.
// Four independent sync streams per SM hide the L2-flag/exchange latency.
// ---------------------------------------------------------------------------
#define F_WS    0        // 16384 floats (8192 ull): weight k-half [w][cp][256 k']
#define F_H2    16384    // 1024 floats: h2[512] float2 {b0,b1}
#define F_TOT   17408
#define SCAN_SMEM (F_TOT * 4)

// per-set matvec + tree + publish (z store, LN warp partial)
template <int SET>
__device__ __forceinline__ void compute_set(
    const float2* __restrict__ h2s, const ull* __restrict__ wreg,
    const ull* __restrict__ ws, int w, int l, int sel, int sel2, bool actW,
    ull xp, float* zdst, float2* wpartS)
{
    ull A0 = 0, A1 = 0, A2 = 0, A3 = 0;      // colpairs 0..3
#pragma unroll
    for (int i = 0; i < 16; ++i) {
        float2 hv = h2s[i * 32 + l];          // coalesced LDS.64
        float hb  = SET ? hv.y : hv.x;
        ull hbb = pack2(hb, hb);
        ull w0, w1, w2, w3;
        if (i < 8) {
            w0 = wreg[i * 4 + 0]; w1 = wreg[i * 4 + 1];
            w2 = wreg[i * 4 + 2]; w3 = wreg[i * 4 + 3];
        } else {
            int o = w * 1024 + 32 * (i - 8) + l;
            w0 = ws[o]; w1 = ws[o + 256]; w2 = ws[o + 512]; w3 = ws[o + 768];
        }
        ffma2(A0, w0, hbb); ffma2(A1, w1, hbb);
        ffma2(A2, w2, hbb); ffma2(A3, w3, hbb);
    }
    // L16: fold colpair-group (keep {2sel, 2sel+1})
    ull B0, B1;
    {
        ull k0 = sel ? A2 : A0, g0 = sel ? A0 : A2;
        ull k1 = sel ? A3 : A1, g1 = sel ? A1 : A3;
        B0 = add2(k0, __shfl_xor_sync(0xffffffffu, g0, 16));
        B1 = add2(k1, __shfl_xor_sync(0xffffffffu, g1, 16));
    }
    // L8: fold colpair (keep 2sel+sel2)
    ull C;
    {
        ull k = sel2 ? B1 : B0, gv = sel2 ? B0 : B1;
        C = add2(k, __shfl_xor_sync(0xffffffffu, gv, 8));
    }
    C = add2(C, __shfl_xor_sync(0xffffffffu, C, 4));
    C = add2(C, __shfl_xor_sync(0xffffffffu, C, 2));
    C = add2(C, __shfl_xor_sync(0xffffffffu, C, 1));

    float s = 0.f, qs = 0.f;
    if (actW) {                               // lanes 0,8,16,24
        C = add2(C, xp);
        float2 zz = unpack2(C);
        stcg64(zdst, C);
        s  = zz.x + zz.y;
        qs = zz.x * zz.x + zz.y * zz.y;
    }
    s  += __shfl_xor_sync(0xffffffffu, s, 8);
    qs += __shfl_xor_sync(0xffffffffu, qs, 8);
    s  += __shfl_xor_sync(0xffffffffu, s, 16);
    qs += __shfl_xor_sync(0xffffffffu, qs, 16);
    if (l == 0) wpartS[w] = make_float2(s, qs);
}

__global__ void __launch_bounds__(256, 2) scan_kernel(
    const float* __restrict__ h0, const float* __restrict__ Wh,
    const float* __restrict__ gamma, const float* __restrict__ beta,
    float* __restrict__ out) {
    extern __shared__ float smf[];
    ull*    ws  = (ull*)(smf + F_WS);
    float2* h2s = (float2*)(smf + F_H2);
    __shared__ float2 wpart[2][8];            // [set][warp]

    const int tid   = threadIdx.x;
    const int w     = tid >> 5;
    const int l     = tid & 31;
    const int g     = blockIdx.x >> 3;
    const int rank  = blockIdx.x & 7;
    const int jbase = rank * 64;
    const int bbase = g * 2;

    const int  sel  = l >> 4;
    const int  sel2 = (l >> 3) & 1;
    const bool actW = ((l & 7) == 0);         // 4 writer lanes per warp

    // ---- prologue: weights k<256 -> regs, k>=256 -> SMEM ----
    ull wreg[32];
#pragma unroll
    for (int i = 0; i < 8; ++i)
#pragma unroll
        for (int cp = 0; cp < 4; ++cp)
            wreg[i * 4 + cp] =
                *(const ull*)&Wh[(size_t)(32 * i + l) * HH + jbase + w * 8 + cp * 2];
#pragma unroll
    for (int i = 0; i < 8; ++i)
#pragma unroll
        for (int cp = 0; cp < 4; ++cp)
            ws[w * 1024 + cp * 256 + 32 * i + l] =
                *(const ull*)&Wh[(size_t)(256 + 32 * i + l) * HH + jbase + w * 8 + cp * 2];

    h2s[2 * tid]     = make_float2(h0[(size_t)(bbase + 0) * HH + 2 * tid],
                                   h0[(size_t)(bbase + 1) * HH + 2 * tid]);
    h2s[2 * tid + 1] = make_float2(h0[(size_t)(bbase + 0) * HH + 2 * tid + 1],
                                   h0[(size_t)(bbase + 1) * HH + 2 * tid + 1]);
    const float gm0 = __ldg(&gamma[2 * tid]), gm1 = __ldg(&gamma[2 * tid + 1]);
    const float bt0 = __ldg(&beta[2 * tid]),  bt1 = __ldg(&beta[2 * tid + 1]);

    // writer-lane addressing (colpair cp = l>>3)
    const int j0 = jbase + w * 8 + (l >> 3) * 2;
    const float* xpb0 = &g_xproj[((size_t)(bbase + 0) * TT) * HH + j0];
    const float* xpb1 = &g_xproj[((size_t)(bbase + 1) * TT) * HH + j0];
    float* z0base = &g_z[g][0][0][j0];
    float* z1base = &g_z[g][1][0][j0];
    unsigned* flag0 = &g_flag[g][0];
    unsigned* flag1 = &g_flag[g][1];
    const bool owner = ((tid >> 5) == rank);

    __syncthreads();
    ull xp0 = actW ? ldcg64(xpb0) : 0ull;     // prefetch t = 0
    ull xp1 = actW ? ldcg64(xpb1) : 0ull;

    for (int t = 0; t < TT; ++t) {
        const int buf = t & 1;
        const unsigned target = 8u * (unsigned)(t + 1);

        // ---- C0: batch 0 ----
        compute_set<0>(h2s, wreg, ws, w, l, sel, sel2, actW,
                       xp0, z0base + buf * HH, wpart[0]);
        __syncthreads();   // bar1: z0 stores + wpart0 done
        if (w == 0) {      // warp-uniform reduce + publish set 0
            float2 e = wpart[0][l & 7];
            float ss = e.x, qq = e.y;
#pragma unroll
            for (int o = 1; o <= 4; o <<= 1) {
                ss += __shfl_xor_sync(0xffffffffu, ss, o);
                qq += __shfl_xor_sync(0xffffffffu, qq, o);
            }
            if (l == 0) {
                stcg_f2(&g_part[g][0][buf][rank], ss, qq);
                red_rel_add(flag0, 1u);
            }
        }

        // ---- C1: batch 1 (hides set-0 flag/fabric latency) ----
        compute_set<1>(h2s, wreg, ws, w, l, sel, sel2, actW,
                       xp1, z1base + buf * HH, wpart[1]);
        if (actW) {        // prefetch next step's xproj
            xp0 = (t + 1 < TT) ? ldcg64(xpb0 + (size_t)(t + 1) * HH) : 0ull;
            xp1 = (t + 1 < TT) ? ldcg64(xpb1 + (size_t)(t + 1) * HH) : 0ull;
        }
        __syncthreads();   // bar2: z1 stores + wpart1 done
        if (w == 0) {
            float2 e = wpart[1][l & 7];
            float ss = e.x, qq = e.y;
#pragma unroll
            for (int o = 1; o <= 4; o <<= 1) {
                ss += __shfl_xor_sync(0xffffffffu, ss, o);
                qq += __shfl_xor_sync(0xffffffffu, qq, o);
            }
            if (l == 0) {
                stcg_f2(&g_part[g][1][buf][rank], ss, qq);
                red_rel_add(flag1, 1u);
            }
            unsigned v;                      // spin set 0
            do { v = ld_acq(flag0); } while (v < target);
        }
        __syncthreads();   // bar3: set-0 data globally ready

        // ---- E0: batch 0 epilogue ----
        {
            ull za = ldcg64(&g_z[g][0][buf][2 * tid]);
            const float4* pp = (const float4*)&g_part[g][0][buf][0];
            float ss = 0.f, qq = 0.f;
#pragma unroll
            for (int c = 0; c < 4; ++c) {
                float4 v = ldcg128(pp + c);
                ss += v.x + v.z; qq += v.y + v.w;
            }
            float m = ss * (1.0f / 512.0f);
            float r = rsqrtf(qq * (1.0f / 512.0f) - m * m + 1e-3f);
            float2 zz = unpack2(za);
            float h00 = ftanh((zz.x - m) * r * gm0 + bt0);
            float h10 = ftanh((zz.y - m) * r * gm1 + bt1);
            h2s[2 * tid].x     = h00;
            h2s[2 * tid + 1].x = h10;
            if (owner) {
                __stcs(&out[((size_t)(bbase + 0) * TT + t) * HH + 2 * tid],     h00);
                __stcs(&out[((size_t)(bbase + 0) * TT + t) * HH + 2 * tid + 1], h10);
            }
        }
        if (w == 0) {       // spin set 1 (after doing E0 work)
            unsigned v;
            do { v = ld_acq(flag1); } while (v < target);
        }
        __syncthreads();   // bar4: set-1 data globally ready

        // ---- E1: batch 1 epilogue ----
        {
            ull zb = ldcg64(&g_z[g][1][buf][2 * tid]);
            const float4* pp = (const float4*)&g_part[g][1][buf][0];
            float ss = 0.f, qq = 0.f;
#pragma unroll
            for (int c = 0; c < 4; ++c) {
                float4 v = ldcg128(pp + c);
                ss += v.x + v.z; qq += v.y + v.w;
            }
            float m = ss * (1.0f / 512.0f);
            float r = rsqrtf(qq * (1.0f / 512.0f) - m * m + 1e-3f);
            float2 zz = unpack2(zb);
            float h01 = ftanh((zz.x - m) * r * gm0 + bt0);
            float h11 = ftanh((zz.y - m) * r * gm1 + bt1);
            h2s[2 * tid].y     = h01;
            h2s[2 * tid + 1].y = h11;
            if (owner) {
                __stcs(&out[((size_t)(bbase + 1) * TT + t) * HH + 2 * tid],     h01);
                __stcs(&out[((size_t)(bbase + 1) * TT + t) * HH + 2 * tid + 1], h11);
            }
        }
        __syncthreads();   // bar5: h2s complete for next step
    }
}

// ---------------------------------------------------------------------------
extern "C" void kernel_launch(void* const* d_in, const int* in_sizes, int n_in,
                              void* d_out, int out_size) {
    const float* inputs = (const float*)d_in[0];  // [64,512,256]
    const float* h0     = (const float*)d_in[1];  // [64,512]
    const float* Wx     = (const float*)d_in[2];  // [256,512]
    const float* Wh     = (const float*)d_in[3];  // [512,512]
    const float* bias   = (const float*)d_in[4];  // [512]
    const float* gamma  = (const float*)d_in[5];  // [512]
    const float* beta   = (const float*)d_in[6];  // [512]
    float* out = (float*)d_out;                   // [64,512,512]

    cudaFuncSetAttribute(scan_kernel,
                         cudaFuncAttributeMaxDynamicSharedMemorySize, SCAN_SMEM);

    dim3 g1(BB * TT / 128, HH / 64);
    xproj_kernel<<<g1, 256>>>(inputs, Wx, bias);   // also resets g_flag
    scan_kernel<<<NG * GC, 256, SCAN_SMEM>>>(h0, Wh, gamma, beta, out);
}